// round 9
// baseline (speedup 1.0000x reference)
#include <cuda_runtime.h>
#include <cuda_fp16.h>
#include <math.h>

#define NN 50000
#define EE 600000
#define DD 128
#define ELLS 96                    // ELL row stride (max supported degree)

// ---------------- scratch (device globals; no allocation allowed) ----------
__device__ float g_dinv[NN];
__device__ int   g_cnt[NN];          // per-dst fill cursor / final count
__device__ int   g_csrc[NN * ELLS];  // ELL: src node per slot
__device__ float g_cw[NN * ELLS];    // ELL: raw edge weight per slot
__device__ unsigned g_h16[NN * 64];  // pre-scaled messages m = h*dinv (half2 pairs)
__device__ float g_agg[NN * DD];     // aggregated features (layer-0 output, f32)
__device__ float g_sc[2 * DD];       // folded BN scale per layer
__device__ float g_sh[2 * DD];       // folded BN shift (incl. bias) per layer
__device__ float g_alpha;            // sigmoid(act_params[0])

// ---------------- prep kernels ----------------------------------------------
__global__ void k_zero() {
    int i = blockIdx.x * blockDim.x + threadIdx.x;
    if (i < NN) g_cnt[i] = 0;
}

// single edge pass: ELL slot fill with raw weight (one atomic per edge)
__global__ void k_fill(const int* __restrict__ src, const int* __restrict__ dst,
                       const float* __restrict__ ew) {
    int e = blockIdx.x * blockDim.x + threadIdx.x;
    if (e >= EE) return;
    int d = dst[e];
    int c = atomicAdd(&g_cnt[d], 1);
    if (c < ELLS) {
        int slot = d * ELLS + c;
        g_csrc[slot] = src[e];
        g_cw[slot] = ew[e];
    }
}

// warp per node: weighted degree = sum of raw slot weights; dinv = rsqrt(deg+1)
__global__ void k_dinv() {
    int t = blockIdx.x * blockDim.x + threadIdx.x;
    int node = t >> 5;
    int lane = t & 31;
    if (node >= NN) return;
    int cnt = g_cnt[node];
    if (cnt > ELLS) cnt = ELLS;
    int beg = node * ELLS;
    float s = 0.f;
    for (int j = lane; j < cnt; j += 32) s += g_cw[beg + j];
#pragma unroll
    for (int off = 16; off > 0; off >>= 1)
        s += __shfl_down_sync(0xFFFFFFFFu, s, off);
    if (lane == 0) g_dinv[node] = rsqrtf(s + 1.0f);   // +1 = self-loop weight
}

__global__ void k_bnprep(const float* __restrict__ b0, const float* __restrict__ ga0,
                         const float* __restrict__ be0, const float* __restrict__ m0,
                         const float* __restrict__ v0,
                         const float* __restrict__ b1, const float* __restrict__ ga1,
                         const float* __restrict__ be1, const float* __restrict__ m1,
                         const float* __restrict__ v1,
                         const float* __restrict__ act) {
    int t = threadIdx.x;
    if (t < DD) {
        float sc = ga0[t] * rsqrtf(v0[t] + 1e-5f);
        g_sc[t] = sc;
        g_sh[t] = be0[t] + (b0[t] - m0[t]) * sc;
    } else if (t < 2 * DD) {
        int c = t - DD;
        float sc = ga1[c] * rsqrtf(v1[c] + 1e-5f);
        g_sc[t] = sc;
        g_sh[t] = be1[c] + (b1[c] - m1[c]) * sc;
    }
    if (t == 0) g_alpha = 1.0f / (1.0f + expf(-act[0]));
}

// ---------------- tf32 tensor-core GEMM -------------------------------------
// H16 = (A' @ W) * dinv[row]   (pre-scaled fp16 messages)
// A' = A (PRE_POST=0) or adaptive-act(BN0(A)) applied during staging.
#define SMS 132                                    // smem row stride (floats)
#define GEMM_SMEM ((64 * SMS + 128 * SMS) * 4)     // As + Ws

__device__ __forceinline__ unsigned f2tf32(float f) {
    unsigned u;
    asm("cvt.rna.tf32.f32 %0, %1;" : "=r"(u) : "f"(f));
    return u;
}

template <int PRE_POST>
__global__ __launch_bounds__(256) void k_gemm(const float* __restrict__ A,
                                              const float* __restrict__ W,
                                              unsigned* __restrict__ H16, int n) {
    extern __shared__ unsigned sm[];
    unsigned* As = sm;              // [64][SMS]
    unsigned* Ws = sm + 64 * SMS;   // [128][SMS]

    int tid = threadIdx.x;
    int row0 = blockIdx.x * 64;

    // ---- stage W (tf32-converted) ----
    const float4* W4 = (const float4*)W;
#pragma unroll
    for (int i = 0; i < 16; i++) {
        int idx = tid + i * 256;        // 4096 float4 = 128 rows x 32
        int r = idx >> 5, c = idx & 31;
        float4 v = W4[idx];
        uint4 u = make_uint4(f2tf32(v.x), f2tf32(v.y), f2tf32(v.z), f2tf32(v.w));
        *(uint4*)&Ws[r * SMS + c * 4] = u;
    }

    // ---- stage A tile (+ fused BN0 + adaptive act for layer 1), tf32 ----
    float alpha = g_alpha;
    const float4* A4 = (const float4*)A;
#pragma unroll
    for (int i = 0; i < 8; i++) {
        int idx = tid + i * 256;        // 2048 float4 = 64 rows x 32
        int r = idx >> 5, c = idx & 31;
        float4 v = make_float4(0.f, 0.f, 0.f, 0.f);
        if (row0 + r < n) v = A4[(size_t)(row0 + r) * 32 + c];
        if (PRE_POST) {
            float* pv = (float*)&v;
#pragma unroll
            for (int j = 0; j < 4; j++) {
                float t = pv[j] * g_sc[c * 4 + j] + g_sh[c * 4 + j];
                float relu = fmaxf(t, 0.f);
                float gelu = 0.5f * t * (1.f + erff(t * 0.70710678118654752f));
                pv[j] = alpha * relu + (1.f - alpha) * gelu;
            }
        }
        uint4 u = make_uint4(f2tf32(v.x), f2tf32(v.y), f2tf32(v.z), f2tf32(v.w));
        *(uint4*)&As[r * SMS + c * 4] = u;
    }
    __syncthreads();

    int wid = tid >> 5;
    int lane = tid & 31;
    int rw = (wid & 3) * 16;       // row band within tile
    int cw = (wid >> 2) * 64;      // col half
    int q = lane >> 2;             // 0..7
    int m = lane & 3;              // 0..3

    float acc[8][4];
#pragma unroll
    for (int nt = 0; nt < 8; nt++)
#pragma unroll
        for (int j = 0; j < 4; j++) acc[nt][j] = 0.f;

#pragma unroll
    for (int kt = 0; kt < 16; kt++) {
        int k0 = kt * 8;
        const unsigned* Ar = &As[(rw + q) * SMS + k0 + m];
        unsigned a0 = Ar[0];
        unsigned a2 = Ar[4];
        unsigned a1 = Ar[8 * SMS];
        unsigned a3 = Ar[8 * SMS + 4];
#pragma unroll
        for (int nt = 0; nt < 8; nt++) {
            int n0 = cw + nt * 8;
            unsigned b0 = Ws[(k0 + m) * SMS + n0 + q];
            unsigned b1 = Ws[(k0 + m + 4) * SMS + n0 + q];
            asm("mma.sync.aligned.m16n8k8.row.col.f32.tf32.tf32.f32 "
                "{%0,%1,%2,%3}, {%4,%5,%6,%7}, {%8,%9}, {%0,%1,%2,%3};"
                : "+f"(acc[nt][0]), "+f"(acc[nt][1]), "+f"(acc[nt][2]), "+f"(acc[nt][3])
                : "r"(a0), "r"(a1), "r"(a2), "r"(a3), "r"(b0), "r"(b1));
        }
    }

    // ---- epilogue: store fp16 messages pre-scaled by dinv[row] ----
    int r_lo = row0 + rw + q;       // rows r_lo and r_lo+8
    float d0 = (r_lo < n) ? g_dinv[r_lo] : 0.f;
    float d1 = (r_lo + 8 < n) ? g_dinv[r_lo + 8] : 0.f;
#pragma unroll
    for (int nt = 0; nt < 8; nt++) {
        int col = cw + nt * 8 + 2 * m;
        if (r_lo < n) {
            __half2 hv = __floats2half2_rn(acc[nt][0] * d0, acc[nt][1] * d0);
            H16[(size_t)r_lo * 64 + (col >> 1)] = *(unsigned*)&hv;
        }
        if (r_lo + 8 < n) {
            __half2 hv = __floats2half2_rn(acc[nt][2] * d1, acc[nt][3] * d1);
            H16[(size_t)(r_lo + 8) * 64 + (col >> 1)] = *(unsigned*)&hv;
        }
    }
}

// ---------------- gather: one warp per destination node --------------------
// acc = m[node] + sum_j ew_j * m[src_j];  result *= dinv[node];
// POST: apply BN1 before store. (m = h*dinv pre-scaled messages, fp16.)
template <int POST>
__global__ __launch_bounds__(256) void k_gather(const uint2* __restrict__ h,
                                                float4* __restrict__ out) {
    int t = blockIdx.x * blockDim.x + threadIdx.x;
    int node = t >> 5;
    int lane = t & 31;
    if (node >= NN) return;

    int beg = node * ELLS;
    int cnt = g_cnt[node];
    if (cnt > ELLS) cnt = ELLS;
    int end = beg + cnt;

    uint2 sr = h[(size_t)node * 32 + lane];
    float2 slo = __half22float2(*(__half2*)&sr.x);
    float2 shi = __half22float2(*(__half2*)&sr.y);
    float4 acc = make_float4(slo.x, slo.y, shi.x, shi.y);

    int j = beg;
    for (; j + 3 < end; j += 4) {
        int s0 = __ldg(&g_csrc[j]),     s1 = __ldg(&g_csrc[j + 1]);
        int s2 = __ldg(&g_csrc[j + 2]), s3 = __ldg(&g_csrc[j + 3]);
        float w0 = __ldg(&g_cw[j]),     w1 = __ldg(&g_cw[j + 1]);
        float w2 = __ldg(&g_cw[j + 2]), w3 = __ldg(&g_cw[j + 3]);
        uint2 r0 = h[(size_t)s0 * 32 + lane];
        uint2 r1 = h[(size_t)s1 * 32 + lane];
        uint2 r2 = h[(size_t)s2 * 32 + lane];
        uint2 r3 = h[(size_t)s3 * 32 + lane];
        float2 l0 = __half22float2(*(__half2*)&r0.x), h0 = __half22float2(*(__half2*)&r0.y);
        float2 l1 = __half22float2(*(__half2*)&r1.x), h1 = __half22float2(*(__half2*)&r1.y);
        float2 l2 = __half22float2(*(__half2*)&r2.x), h2 = __half22float2(*(__half2*)&r2.y);
        float2 l3 = __half22float2(*(__half2*)&r3.x), h3 = __half22float2(*(__half2*)&r3.y);
        acc.x += w0 * l0.x + w1 * l1.x + w2 * l2.x + w3 * l3.x;
        acc.y += w0 * l0.y + w1 * l1.y + w2 * l2.y + w3 * l3.y;
        acc.z += w0 * h0.x + w1 * h1.x + w2 * h2.x + w3 * h3.x;
        acc.w += w0 * h0.y + w1 * h1.y + w2 * h2.y + w3 * h3.y;
    }
    for (; j < end; j++) {
        int s = __ldg(&g_csrc[j]);
        float w = __ldg(&g_cw[j]);
        uint2 r = h[(size_t)s * 32 + lane];
        float2 lo = __half22float2(*(__half2*)&r.x);
        float2 hi = __half22float2(*(__half2*)&r.y);
        acc.x += w * lo.x;
        acc.y += w * lo.y;
        acc.z += w * hi.x;
        acc.w += w * hi.y;
    }

    float dn = g_dinv[node];
    acc.x *= dn; acc.y *= dn; acc.z *= dn; acc.w *= dn;

    if (POST) {
        int c0 = lane * 4 + DD;   // layer-1 BN params
        acc.x = acc.x * g_sc[c0 + 0] + g_sh[c0 + 0];
        acc.y = acc.y * g_sc[c0 + 1] + g_sh[c0 + 1];
        acc.z = acc.z * g_sc[c0 + 2] + g_sh[c0 + 2];
        acc.w = acc.w * g_sc[c0 + 3] + g_sh[c0 + 3];
    }
    out[(size_t)node * 32 + lane] = acc;
}

// ---------------- launch ----------------------------------------------------
extern "C" void kernel_launch(void* const* d_in, const int* in_sizes, int n_in,
                              void* d_out, int out_size) {
    const float* x  = (const float*)d_in[0];
    const int*   ei = (const int*)d_in[1];     // [2,E]: row0=src, row1=dst
    const float* ew = (const float*)d_in[2];
    const float* W0 = (const float*)d_in[3];
    const float* b0 = (const float*)d_in[4];
    const float* W1 = (const float*)d_in[5];
    const float* b1 = (const float*)d_in[6];
    const float* ga0 = (const float*)d_in[7];
    const float* be0 = (const float*)d_in[8];
    const float* m0  = (const float*)d_in[9];
    const float* v0  = (const float*)d_in[10];
    const float* ga1 = (const float*)d_in[11];
    const float* be1 = (const float*)d_in[12];
    const float* m1  = (const float*)d_in[13];
    const float* v1  = (const float*)d_in[14];
    const float* act = (const float*)d_in[15];
    float* out = (float*)d_out;

    const int* src = ei;
    const int* dst = ei + EE;

    unsigned* hD; cudaGetSymbolAddress((void**)&hD, g_h16);
    float* aggD;  cudaGetSymbolAddress((void**)&aggD, g_agg);

    cudaFuncSetAttribute(k_gemm<0>, cudaFuncAttributeMaxDynamicSharedMemorySize, GEMM_SMEM);
    cudaFuncSetAttribute(k_gemm<1>, cudaFuncAttributeMaxDynamicSharedMemorySize, GEMM_SMEM);

    const int B = 256;
    int gN    = (NN + B - 1) / B;
    int gE    = (EE + B - 1) / B;
    int gGth  = (NN * 32 + B - 1) / B;
    int gGemm = (NN + 63) / 64;

    // graph prep + ELL build (raw weights; no norm precompute)
    k_zero<<<gN, B>>>();
    k_fill<<<gE, B>>>(src, dst, ew);
    k_dinv<<<gGth, B>>>();
    k_bnprep<<<1, 256>>>(b0, ga0, be0, m0, v0, b1, ga1, be1, m1, v1, act);

    // layer 0: m = (x@W0)*dinv; agg = dinv * (m_self + sum ew*m_src)
    k_gemm<0><<<gGemm, B, GEMM_SMEM>>>(x, W0, hD, NN);
    k_gather<0><<<gGth, B>>>((const uint2*)hD, (float4*)aggD);

    // layer 1: m = (act(BN0(agg))@W1)*dinv; out = BN1(dinv*(m_self + sum ew*m_src))
    k_gemm<1><<<gGemm, B, GEMM_SMEM>>>(aggD, W1, hD, NN);
    k_gather<1><<<gGth, B>>>((const uint2*)hD, (float4*)out);
}

// round 10
// speedup vs baseline: 1.0552x; 1.0552x over previous
#include <cuda_runtime.h>
#include <cuda_fp16.h>
#include <math.h>

#define NN 50000
#define EE 600000
#define DD 128
#define ELLS 96                    // ELL row stride (max supported degree)

// ---------------- scratch (device globals; no allocation allowed) ----------
__device__ float g_dinv[NN];
__device__ int   g_cnt[NN];          // per-dst fill cursor / final count
__device__ int   g_csrc[NN * ELLS];  // ELL: src node per slot
__device__ float g_cw[NN * ELLS];    // ELL: raw ew -> fully normalized weight
__device__ unsigned g_h16[NN * 64];  // raw messages h as half2 pairs
__device__ float g_agg[NN * DD];     // aggregated features (layer-0 output, f32)
__device__ float g_sc[2 * DD];       // folded BN scale per layer
__device__ float g_sh[2 * DD];       // folded BN shift (incl. bias) per layer
__device__ float g_alpha;            // sigmoid(act_params[0])

// ---------------- prep kernels (side stream) --------------------------------
__global__ void k_zero() {
    int i = blockIdx.x * blockDim.x + threadIdx.x;
    if (i < NN) g_cnt[i] = 0;
}

// ELL slot fill with raw weight; 4 independent edges per thread (MLP)
__global__ void k_fill(const int* __restrict__ src, const int* __restrict__ dst,
                       const float* __restrict__ ew) {
    int t = blockIdx.x * blockDim.x + threadIdx.x;
    int stride = gridDim.x * blockDim.x;
    int   dd[4], ss[4];
    float ww[4];
    bool  vv[4];
#pragma unroll
    for (int i = 0; i < 4; i++) {
        int e = t + i * stride;
        vv[i] = (e < EE);
        if (vv[i]) {
            dd[i] = dst[e];
            ss[i] = src[e];
            ww[i] = ew[e];
        }
    }
#pragma unroll
    for (int i = 0; i < 4; i++) {
        if (vv[i]) {
            int c = atomicAdd(&g_cnt[dd[i]], 1);
            if (c < ELLS) {
                int slot = dd[i] * ELLS + c;
                g_csrc[slot] = ss[i];
                g_cw[slot] = ww[i];
            }
        }
    }
}

// warp per node: weighted degree = sum of raw slot weights; dinv = rsqrt(deg+1)
__global__ void k_dinv() {
    int t = blockIdx.x * blockDim.x + threadIdx.x;
    int node = t >> 5;
    int lane = t & 31;
    if (node >= NN) return;
    int cnt = g_cnt[node];
    if (cnt > ELLS) cnt = ELLS;
    int beg = node * ELLS;
    float s = 0.f;
    for (int j = lane; j < cnt; j += 32) s += g_cw[beg + j];
#pragma unroll
    for (int off = 16; off > 0; off >>= 1)
        s += __shfl_down_sync(0xFFFFFFFFu, s, off);
    if (lane == 0) g_dinv[node] = rsqrtf(s + 1.0f);   // +1 = self-loop weight
}

// warp per node: cw[slot] = dinv[src] * ew_raw * dinv[node]
__global__ void k_wnorm() {
    int t = blockIdx.x * blockDim.x + threadIdx.x;
    int node = t >> 5;
    int lane = t & 31;
    if (node >= NN) return;
    int cnt = g_cnt[node];
    if (cnt > ELLS) cnt = ELLS;
    float dd = g_dinv[node];
    int beg = node * ELLS;
    for (int j = lane; j < cnt; j += 32) {
        int s = g_csrc[beg + j];
        g_cw[beg + j] *= g_dinv[s] * dd;
    }
}

__global__ void k_bnprep(const float* __restrict__ b0, const float* __restrict__ ga0,
                         const float* __restrict__ be0, const float* __restrict__ m0,
                         const float* __restrict__ v0,
                         const float* __restrict__ b1, const float* __restrict__ ga1,
                         const float* __restrict__ be1, const float* __restrict__ m1,
                         const float* __restrict__ v1,
                         const float* __restrict__ act) {
    int t = threadIdx.x;
    if (t < DD) {
        float sc = ga0[t] * rsqrtf(v0[t] + 1e-5f);
        g_sc[t] = sc;
        g_sh[t] = be0[t] + (b0[t] - m0[t]) * sc;
    } else if (t < 2 * DD) {
        int c = t - DD;
        float sc = ga1[c] * rsqrtf(v1[c] + 1e-5f);
        g_sc[t] = sc;
        g_sh[t] = be1[c] + (b1[c] - m1[c]) * sc;
    }
    if (t == 0) g_alpha = 1.0f / (1.0f + expf(-act[0]));
}

// ---------------- tf32 tensor-core GEMM -------------------------------------
// H16 = A' @ W   (raw fp16 messages; graph-independent)
// A' = A (PRE_POST=0) or adaptive-act(BN0(A)) applied during staging.
#define SMS 132                                    // smem row stride (floats)
#define GEMM_SMEM ((64 * SMS + 128 * SMS) * 4)     // As + Ws

__device__ __forceinline__ unsigned f2tf32(float f) {
    unsigned u;
    asm("cvt.rna.tf32.f32 %0, %1;" : "=r"(u) : "f"(f));
    return u;
}

template <int PRE_POST>
__global__ __launch_bounds__(256) void k_gemm(const float* __restrict__ A,
                                              const float* __restrict__ W,
                                              unsigned* __restrict__ H16, int n) {
    extern __shared__ unsigned sm[];
    unsigned* As = sm;              // [64][SMS]
    unsigned* Ws = sm + 64 * SMS;   // [128][SMS]

    int tid = threadIdx.x;
    int row0 = blockIdx.x * 64;

    // ---- stage W (tf32-converted) ----
    const float4* W4 = (const float4*)W;
#pragma unroll
    for (int i = 0; i < 16; i++) {
        int idx = tid + i * 256;        // 4096 float4 = 128 rows x 32
        int r = idx >> 5, c = idx & 31;
        float4 v = W4[idx];
        uint4 u = make_uint4(f2tf32(v.x), f2tf32(v.y), f2tf32(v.z), f2tf32(v.w));
        *(uint4*)&Ws[r * SMS + c * 4] = u;
    }

    // ---- stage A tile (+ fused BN0 + adaptive act for layer 1), tf32 ----
    float alpha = g_alpha;
    const float4* A4 = (const float4*)A;
#pragma unroll
    for (int i = 0; i < 8; i++) {
        int idx = tid + i * 256;        // 2048 float4 = 64 rows x 32
        int r = idx >> 5, c = idx & 31;
        float4 v = make_float4(0.f, 0.f, 0.f, 0.f);
        if (row0 + r < n) v = A4[(size_t)(row0 + r) * 32 + c];
        if (PRE_POST) {
            float* pv = (float*)&v;
#pragma unroll
            for (int j = 0; j < 4; j++) {
                float t = pv[j] * g_sc[c * 4 + j] + g_sh[c * 4 + j];
                float relu = fmaxf(t, 0.f);
                float gelu = 0.5f * t * (1.f + erff(t * 0.70710678118654752f));
                pv[j] = alpha * relu + (1.f - alpha) * gelu;
            }
        }
        uint4 u = make_uint4(f2tf32(v.x), f2tf32(v.y), f2tf32(v.z), f2tf32(v.w));
        *(uint4*)&As[r * SMS + c * 4] = u;
    }
    __syncthreads();

    int wid = tid >> 5;
    int lane = tid & 31;
    int rw = (wid & 3) * 16;       // row band within tile
    int cw = (wid >> 2) * 64;      // col half
    int q = lane >> 2;             // 0..7
    int m = lane & 3;              // 0..3

    float acc[8][4];
#pragma unroll
    for (int nt = 0; nt < 8; nt++)
#pragma unroll
        for (int j = 0; j < 4; j++) acc[nt][j] = 0.f;

#pragma unroll
    for (int kt = 0; kt < 16; kt++) {
        int k0 = kt * 8;
        const unsigned* Ar = &As[(rw + q) * SMS + k0 + m];
        unsigned a0 = Ar[0];
        unsigned a2 = Ar[4];
        unsigned a1 = Ar[8 * SMS];
        unsigned a3 = Ar[8 * SMS + 4];
#pragma unroll
        for (int nt = 0; nt < 8; nt++) {
            int n0 = cw + nt * 8;
            unsigned b0 = Ws[(k0 + m) * SMS + n0 + q];
            unsigned b1 = Ws[(k0 + m + 4) * SMS + n0 + q];
            asm("mma.sync.aligned.m16n8k8.row.col.f32.tf32.tf32.f32 "
                "{%0,%1,%2,%3}, {%4,%5,%6,%7}, {%8,%9}, {%0,%1,%2,%3};"
                : "+f"(acc[nt][0]), "+f"(acc[nt][1]), "+f"(acc[nt][2]), "+f"(acc[nt][3])
                : "r"(a0), "r"(a1), "r"(a2), "r"(a3), "r"(b0), "r"(b1));
        }
    }

    // ---- epilogue: store raw fp16 message pairs ----
    int r_lo = row0 + rw + q;       // rows r_lo and r_lo+8
#pragma unroll
    for (int nt = 0; nt < 8; nt++) {
        int col = cw + nt * 8 + 2 * m;
        if (r_lo < n) {
            __half2 hv = __floats2half2_rn(acc[nt][0], acc[nt][1]);
            H16[(size_t)r_lo * 64 + (col >> 1)] = *(unsigned*)&hv;
        }
        if (r_lo + 8 < n) {
            __half2 hv = __floats2half2_rn(acc[nt][2], acc[nt][3]);
            H16[(size_t)(r_lo + 8) * 64 + (col >> 1)] = *(unsigned*)&hv;
        }
    }
}

// ---------------- gather: one warp per destination node --------------------
// acc = dinv^2 * m[node] + sum_j cw_j * m[src_j]   (cw fully normalized)
// POST: apply BN1 before store.
template <int POST>
__global__ __launch_bounds__(256) void k_gather(const uint2* __restrict__ h,
                                                float4* __restrict__ out) {
    int t = blockIdx.x * blockDim.x + threadIdx.x;
    int node = t >> 5;
    int lane = t & 31;
    if (node >= NN) return;

    int beg = node * ELLS;
    int cnt = g_cnt[node];
    if (cnt > ELLS) cnt = ELLS;
    int end = beg + cnt;

    float d = g_dinv[node];
    d *= d;
    uint2 sr = h[(size_t)node * 32 + lane];
    float2 slo = __half22float2(*(__half2*)&sr.x);
    float2 shi = __half22float2(*(__half2*)&sr.y);
    float4 acc = make_float4(slo.x * d, slo.y * d, shi.x * d, shi.y * d);

    int j = beg;
    for (; j + 3 < end; j += 4) {
        int s0 = __ldg(&g_csrc[j]),     s1 = __ldg(&g_csrc[j + 1]);
        int s2 = __ldg(&g_csrc[j + 2]), s3 = __ldg(&g_csrc[j + 3]);
        float w0 = __ldg(&g_cw[j]),     w1 = __ldg(&g_cw[j + 1]);
        float w2 = __ldg(&g_cw[j + 2]), w3 = __ldg(&g_cw[j + 3]);
        uint2 r0 = h[(size_t)s0 * 32 + lane];
        uint2 r1 = h[(size_t)s1 * 32 + lane];
        uint2 r2 = h[(size_t)s2 * 32 + lane];
        uint2 r3 = h[(size_t)s3 * 32 + lane];
        float2 l0 = __half22float2(*(__half2*)&r0.x), h0 = __half22float2(*(__half2*)&r0.y);
        float2 l1 = __half22float2(*(__half2*)&r1.x), h1 = __half22float2(*(__half2*)&r1.y);
        float2 l2 = __half22float2(*(__half2*)&r2.x), h2 = __half22float2(*(__half2*)&r2.y);
        float2 l3 = __half22float2(*(__half2*)&r3.x), h3 = __half22float2(*(__half2*)&r3.y);
        acc.x += w0 * l0.x + w1 * l1.x + w2 * l2.x + w3 * l3.x;
        acc.y += w0 * l0.y + w1 * l1.y + w2 * l2.y + w3 * l3.y;
        acc.z += w0 * h0.x + w1 * h1.x + w2 * h2.x + w3 * h3.x;
        acc.w += w0 * h0.y + w1 * h1.y + w2 * h2.y + w3 * h3.y;
    }
    for (; j < end; j++) {
        int s = __ldg(&g_csrc[j]);
        float w = __ldg(&g_cw[j]);
        uint2 r = h[(size_t)s * 32 + lane];
        float2 lo = __half22float2(*(__half2*)&r.x);
        float2 hi = __half22float2(*(__half2*)&r.y);
        acc.x += w * lo.x;
        acc.y += w * lo.y;
        acc.z += w * hi.x;
        acc.w += w * hi.y;
    }

    if (POST) {
        int c0 = lane * 4 + DD;   // layer-1 BN params
        acc.x = acc.x * g_sc[c0 + 0] + g_sh[c0 + 0];
        acc.y = acc.y * g_sc[c0 + 1] + g_sh[c0 + 1];
        acc.z = acc.z * g_sc[c0 + 2] + g_sh[c0 + 2];
        acc.w = acc.w * g_sc[c0 + 3] + g_sh[c0 + 3];
    }
    out[(size_t)node * 32 + lane] = acc;
}

// ---------------- launch ----------------------------------------------------
extern "C" void kernel_launch(void* const* d_in, const int* in_sizes, int n_in,
                              void* d_out, int out_size) {
    const float* x  = (const float*)d_in[0];
    const int*   ei = (const int*)d_in[1];     // [2,E]: row0=src, row1=dst
    const float* ew = (const float*)d_in[2];
    const float* W0 = (const float*)d_in[3];
    const float* b0 = (const float*)d_in[4];
    const float* W1 = (const float*)d_in[5];
    const float* b1 = (const float*)d_in[6];
    const float* ga0 = (const float*)d_in[7];
    const float* be0 = (const float*)d_in[8];
    const float* m0  = (const float*)d_in[9];
    const float* v0  = (const float*)d_in[10];
    const float* ga1 = (const float*)d_in[11];
    const float* be1 = (const float*)d_in[12];
    const float* m1  = (const float*)d_in[13];
    const float* v1  = (const float*)d_in[14];
    const float* act = (const float*)d_in[15];
    float* out = (float*)d_out;

    const int* src = ei;
    const int* dst = ei + EE;

    unsigned* hD; cudaGetSymbolAddress((void**)&hD, g_h16);
    float* aggD;  cudaGetSymbolAddress((void**)&aggD, g_agg);

    cudaFuncSetAttribute(k_gemm<0>, cudaFuncAttributeMaxDynamicSharedMemorySize, GEMM_SMEM);
    cudaFuncSetAttribute(k_gemm<1>, cudaFuncAttributeMaxDynamicSharedMemorySize, GEMM_SMEM);

    // side stream + fork/join events (created once; capture-safe fork pattern)
    static cudaStream_t sA = nullptr;
    static cudaEvent_t evFork = nullptr, evJoin = nullptr;
    if (sA == nullptr) {
        cudaStreamCreateWithFlags(&sA, cudaStreamNonBlocking);
        cudaEventCreateWithFlags(&evFork, cudaEventDisableTiming);
        cudaEventCreateWithFlags(&evJoin, cudaEventDisableTiming);
    }

    const int B = 256;
    int gN    = (NN + B - 1) / B;
    int gFill = (EE + 4 * B - 1) / (4 * B);
    int gGth  = (NN * 32 + B - 1) / B;
    int gGemm = (NN + 63) / 64;

    // ---- fork: graph prep on side stream, concurrent with layer-0 GEMM ----
    cudaEventRecord(evFork, 0);
    cudaStreamWaitEvent(sA, evFork, 0);
    k_zero<<<gN, B, 0, sA>>>();
    k_fill<<<gFill, B, 0, sA>>>(src, dst, ew);
    k_dinv<<<gGth, B, 0, sA>>>();
    k_wnorm<<<gGth, B, 0, sA>>>();
    cudaEventRecord(evJoin, sA);

    // ---- main stream: bn prep + layer-0 GEMM (graph-independent) ----
    k_bnprep<<<1, 256>>>(b0, ga0, be0, m0, v0, b1, ga1, be1, m1, v1, act);
    k_gemm<0><<<gGemm, B, GEMM_SMEM>>>(x, W0, hD, NN);

    // ---- join: gather needs ELL + dinv ----
    cudaStreamWaitEvent(0, evJoin, 0);
    k_gather<0><<<gGth, B>>>((const uint2*)hD, (float4*)aggD);

    // layer 1
    k_gemm<1><<<gGemm, B, GEMM_SMEM>>>(aggD, W1, hD, NN);
    k_gather<1><<<gGth, B>>>((const uint2*)hD, (float4*)out);
}